// round 13
// baseline (speedup 1.0000x reference)
#include <cuda_runtime.h>
#include <cuda_fp16.h>
#include <cstdint>

#define D_MODEL 1024
#define N_EXP   16
#define MAX_B   32768
#define THRESH  0.3f

// ---- GEMM tiling (fp16 operands, fp32 accum) ----
#define BM 128
#define BN 128
#define BK 64                               // halfs per k-chunk = 128B per row
#define KPAD_H 72                           // 64 + 8 pad halfs (144B rows, conflict-free)
#define A_STG_BYTES (BM * KPAD_H * 2)       // 18432
#define STG_BYTES   (2 * A_STG_BYTES)       // 36864 (A + B)
#define NSTG 3
#define NCH (D_MODEL / BK)                  // 16 k-chunks
#define SMEM_TOTAL (NSTG * STG_BYTES)       // 110592 -> 2 CTAs/SM @ 512 thr (221KB/SM)
#define NTILES_MAX (MAX_B / BM + N_EXP)     // 272

// ---------------- device-global scratch ----------------
__device__ int    g_counts[N_EXP];
__device__ int    g_tile[MAX_B];
__device__ int    g_rank[MAX_B];
__device__ int    g_perm[MAX_B];
__device__ float  g_qsig[N_EXP * D_MODEL];
__device__ __half g_xh[(size_t)MAX_B * D_MODEL];             // 64 MB fp16 x
__device__ __half g_wh[(size_t)N_EXP * D_MODEL * D_MODEL];   // 32 MB fp16 W

// ---------------- PTX helpers ----------------
__device__ __forceinline__ uint32_t smem_u32(const void* p) {
    uint32_t a;
    asm("{ .reg .u64 t; cvta.to.shared.u64 t, %1; cvt.u32.u64 %0, t; }" : "=r"(a) : "l"(p));
    return a;
}
__device__ __forceinline__ void cpa16(uint32_t dst, const void* src) {
    asm volatile("cp.async.cg.shared.global [%0], [%1], 16;" :: "r"(dst), "l"(src));
}
#define CP_COMMIT() asm volatile("cp.async.commit_group;" ::: "memory")

__device__ __forceinline__ void mma_f16(float* c, const uint32_t* a, const uint32_t* b) {
    asm volatile(
        "mma.sync.aligned.m16n8k16.row.col.f32.f16.f16.f32 "
        "{%0,%1,%2,%3}, {%4,%5,%6,%7}, {%8,%9}, {%0,%1,%2,%3};"
        : "+f"(c[0]), "+f"(c[1]), "+f"(c[2]), "+f"(c[3])
        : "r"(a[0]), "r"(a[1]), "r"(a[2]), "r"(a[3]), "r"(b[0]), "r"(b[1]));
}
__device__ __forceinline__ void ldsm_x4(uint32_t* r, uint32_t addr) {
    asm volatile("ldmatrix.sync.aligned.m8n8.x4.shared.b16 {%0,%1,%2,%3}, [%4];"
                 : "=r"(r[0]), "=r"(r[1]), "=r"(r[2]), "=r"(r[3]) : "r"(addr));
}

// ---------------- setup: zero counts + quantize signatures ----------------
__global__ void setup_kernel(const float* __restrict__ sig) {
    int i = blockIdx.x * blockDim.x + threadIdx.x;
    if (i < N_EXP) g_counts[i] = 0;
    if (i < N_EXP * D_MODEL) {
        float s = sig[i];
        g_qsig[i] = (s > THRESH) ? 1.0f : ((s < -THRESH) ? -1.0f : 0.0f);
    }
}

// ---------------- W fp32 -> fp16 ----------------
__global__ void convert_w_kernel(const float* __restrict__ W) {
    size_t i = (size_t)(blockIdx.x * blockDim.x + threadIdx.x) * 4;
    if (i < (size_t)N_EXP * D_MODEL * D_MODEL) {
        float4 v = *(const float4*)(W + i);
        half2 h0 = __floats2half2_rn(v.x, v.y);
        half2 h1 = __floats2half2_rn(v.z, v.w);
        *(uint2*)(g_wh + i) = make_uint2(*(uint32_t*)&h0, *(uint32_t*)&h1);
    }
}

// ---------------- router: 4 rows per warp, fused x->fp16 ----------------
__global__ void router_kernel(const float* __restrict__ x, int B) {
    const int tid  = threadIdx.x;
    const int warp = tid >> 5;
    const int lane = tid & 31;
    const int row0 = blockIdx.x * 32 + warp * 4;
    if (row0 >= B) return;

    float acc[4][N_EXP];
#pragma unroll
    for (int r = 0; r < 4; r++)
#pragma unroll
        for (int e = 0; e < N_EXP; e++) acc[r][e] = 0.0f;

    const float4* xr[4];
    __half* xh[4];
#pragma unroll
    for (int r = 0; r < 4; r++) {
        int row = row0 + r < B ? row0 + r : B - 1;
        xr[r] = (const float4*)(x + (size_t)row * D_MODEL);
        xh[r] = g_xh + (size_t)row * D_MODEL;
    }

    for (int kk = lane; kk < D_MODEL / 4; kk += 32) {
        float4 xv[4];
#pragma unroll
        for (int r = 0; r < 4; r++) {
            xv[r] = __ldg(&xr[r][kk]);
            half2 h0 = __floats2half2_rn(xv[r].x, xv[r].y);
            half2 h1 = __floats2half2_rn(xv[r].z, xv[r].w);
            *(uint2*)(xh[r] + kk * 4) = make_uint2(*(uint32_t*)&h0, *(uint32_t*)&h1);
        }
#pragma unroll
        for (int e = 0; e < N_EXP; e++) {
            float4 q = *(const float4*)(g_qsig + e * D_MODEL + kk * 4);
#pragma unroll
            for (int r = 0; r < 4; r++)
                acc[r][e] += xv[r].x * q.x + xv[r].y * q.y + xv[r].z * q.z + xv[r].w * q.w;
        }
    }

#pragma unroll
    for (int r = 0; r < 4; r++) {
#pragma unroll
        for (int e = 0; e < N_EXP; e++) {
#pragma unroll
            for (int off = 16; off >= 1; off >>= 1)
                acc[r][e] += __shfl_xor_sync(0xffffffffu, acc[r][e], off);
        }
        if (lane == 0 && row0 + r < B) {
            int best = 0;
            float bv = acc[r][0];
#pragma unroll
            for (int e = 1; e < N_EXP; e++)
                if (acc[r][e] > bv) { bv = acc[r][e]; best = e; }  // first max wins
            g_tile[row0 + r] = best;
            g_rank[row0 + r] = atomicAdd(&g_counts[best], 1);
        }
    }
}

// ---------------- scatter: offsets recomputed inline from g_counts ----------------
__global__ void scatter_kernel(int B, float* __restrict__ tail) {
    int row = blockIdx.x * blockDim.x + threadIdx.x;
    if (row >= B) return;
    int offs = 0, e = g_tile[row];
#pragma unroll
    for (int i = 0; i < N_EXP; i++)
        if (i < e) offs += g_counts[i];
    g_perm[offs + g_rank[row]] = row;
    if (tail) tail[row] = (float)e;
}

// ---------------- fp16 mma.sync expert GEMM: 512 thr, 16 warps 4x4, 3-stage ring ----
__global__ void __launch_bounds__(512, 2) expert_gemm_mma(
    const float* __restrict__ bias, float* __restrict__ out, int B)
{
    // ---- inline flat-tile scheduler from g_counts (no offsets kernel) ----
    const int bx = blockIdx.x;
    int e = 0, m0 = 0, base = 0, cnt = 0;
    {
        int ts = 0, s = 0;
        bool found = false;
#pragma unroll
        for (int i = 0; i < N_EXP; i++) {
            int c  = g_counts[i];
            int nt = (c + BM - 1) / BM;
            if (!found && bx < ts + nt) { e = i; m0 = (bx - ts) * BM; base = s; cnt = c; found = true; }
            ts += nt; s += c;
        }
        if (!found) return;
    }
    const int n0  = blockIdx.y * BN;
    const int rem = cnt - m0;

    extern __shared__ char smem[];
    const uint32_t sb = smem_u32(smem);

    const int tid  = threadIdx.x;
    const int wid  = tid >> 5;
    const int lane = tid & 31;
    const int warp_m = wid >> 2;           // 0..3 (32-row quarters)
    const int warp_n = wid & 3;            // 0..3 (32-col quarters)

    // ---- loader: threads 0-255 load A (gathered rows), 256-511 load B ----
    const int lt    = tid & 255;
    const int lrow  = lt >> 1;             // 0..127
    const int lsegB = (lt & 1) * 64;       // 0 or 64 within the 128B k-chunk row
    const bool isA  = tid < 256;
    const char* src;
    if (isA) {
        const int arloc = (lrow < rem) ? lrow : (rem - 1);
        src = (const char*)(g_xh + (size_t)__ldg(&g_perm[base + m0 + arloc]) * D_MODEL) + lsegB;
    } else {
        src = (const char*)(g_wh + ((size_t)e * D_MODEL + (size_t)(n0 + lrow)) * D_MODEL) + lsegB;
    }
    const uint32_t dst = sb + (isA ? 0u : (uint32_t)A_STG_BYTES)
                       + (uint32_t)lrow * (KPAD_H * 2) + lsegB;

    // ---- ldmatrix per-lane offsets (halfs, within stage) ----
    const int q8 = lane >> 3;
    const int r8 = lane & 7;
    const uint32_t aoffH = (uint32_t)((warp_m * 32 + (q8 & 1) * 8 + r8) * KPAD_H + (q8 >> 1) * 8);
    const uint32_t boffH = (uint32_t)((warp_n * 32 + (q8 >> 1) * 8 + r8) * KPAD_H + (q8 & 1) * 8);

    // prologue: chunks 0,1 -> stages 0,1
#pragma unroll
    for (int c = 0; c < 2; c++) {
        const uint32_t so = (uint32_t)c * STG_BYTES;
        const char* p = src + (size_t)c * 128;
#pragma unroll
        for (int s = 0; s < 4; s++) cpa16(dst + so + s * 16, p + s * 16);
        CP_COMMIT();
    }

    float acc[2][4][4];
#pragma unroll
    for (int i = 0; i < 2; i++)
#pragma unroll
        for (int j = 0; j < 4; j++)
#pragma unroll
            for (int r = 0; r < 4; r++) acc[i][j][r] = 0.0f;

    int stage = 0;
    for (int c = 0; c < NCH; c++) {
        if (c < NCH - 1) asm volatile("cp.async.wait_group 1;" ::: "memory");
        else             asm volatile("cp.async.wait_group 0;" ::: "memory");
        __syncthreads();                   // single barrier per chunk

        if (c + 2 < NCH) {                 // prefetch c+2 into stage (stage+2)%3
            int fs = stage + 2; if (fs >= NSTG) fs -= NSTG;
            const uint32_t so = (uint32_t)fs * STG_BYTES;
            const char* p = src + (size_t)(c + 2) * 128;
#pragma unroll
            for (int s = 0; s < 4; s++) cpa16(dst + so + s * 16, p + s * 16);
            CP_COMMIT();
        }

        const uint32_t sA = sb + (uint32_t)stage * STG_BYTES;
        const uint32_t sB = sA + A_STG_BYTES;

#pragma unroll
        for (int s = 0; s < 4; s++) {
            const int k0 = s * 16;
            uint32_t af[2][4], bf[4][2];
#pragma unroll
            for (int mf = 0; mf < 2; mf++)
                ldsm_x4(af[mf], sA + (aoffH + (uint32_t)(mf * 16) * KPAD_H + k0) * 2);
#pragma unroll
            for (int p = 0; p < 2; p++) {
                uint32_t bq[4];
                ldsm_x4(bq, sB + (boffH + (uint32_t)(p * 16) * KPAD_H + k0) * 2);
                bf[p * 2 + 0][0] = bq[0]; bf[p * 2 + 0][1] = bq[1];
                bf[p * 2 + 1][0] = bq[2]; bf[p * 2 + 1][1] = bq[3];
            }
#pragma unroll
            for (int mf = 0; mf < 2; mf++)
#pragma unroll
                for (int nf = 0; nf < 4; nf++)
                    mma_f16(acc[mf][nf], af[mf], bf[nf]);
        }

        stage++; if (stage >= NSTG) stage -= NSTG;
    }

    // ---- fused epilogue: +bias, relu, +residual (fp16 cache), scatter ----
    const int t = lane & 3;
    const int g = lane >> 2;
    const float* bias_e = bias + e * D_MODEL;
    float2 bb[4];
#pragma unroll
    for (int nf = 0; nf < 4; nf++)
        bb[nf] = *(const float2*)(bias_e + n0 + warp_n * 32 + nf * 8 + t * 2);

#pragma unroll
    for (int mf = 0; mf < 2; mf++) {
#pragma unroll
        for (int h = 0; h < 2; h++) {
            const int rloc = warp_m * 32 + mf * 16 + g + h * 8;
            if (rloc >= rem) continue;
            const int gr = __ldg(&g_perm[base + m0 + rloc]);
            const __half* xhr = g_xh + (size_t)gr * D_MODEL;
            float*        orow = out + (size_t)gr * D_MODEL;
#pragma unroll
            for (int nf = 0; nf < 4; nf++) {
                const int col = n0 + warp_n * 32 + nf * 8 + t * 2;
                const float2 xx = __half22float2(*(const half2*)(xhr + col));
                float v0 = fmaxf(acc[mf][nf][h * 2 + 0] + bb[nf].x, 0.0f) + xx.x;
                float v1 = fmaxf(acc[mf][nf][h * 2 + 1] + bb[nf].y, 0.0f) + xx.y;
                *(float2*)(orow + col) = make_float2(v0, v1);
            }
        }
    }
}

// ---------------- launch ----------------
extern "C" void kernel_launch(void* const* d_in, const int* in_sizes, int n_in,
                              void* d_out, int out_size) {
    const float* x   = (const float*)d_in[0];
    const float* sig = (const float*)d_in[1];
    const float* W   = (const float*)d_in[2];
    const float* b   = (const float*)d_in[3];
    float* out = (float*)d_out;

    const int B = in_sizes[0] / D_MODEL;

    cudaFuncSetAttribute(expert_gemm_mma,
                         cudaFuncAttributeMaxDynamicSharedMemorySize, SMEM_TOTAL);

    setup_kernel<<<(N_EXP * D_MODEL + 255) / 256, 256>>>(sig);
    convert_w_kernel<<<(N_EXP * D_MODEL * D_MODEL / 4 + 255) / 256, 256>>>(W);
    router_kernel<<<(B + 31) / 32, 256>>>(x, B);

    float* tail = nullptr;
    if ((long long)out_size >= (long long)B * D_MODEL + B)
        tail = out + (size_t)B * D_MODEL;
    scatter_kernel<<<(B + 255) / 256, 256>>>(B, tail);

    dim3 grid(NTILES_MAX, D_MODEL / BN);
    expert_gemm_mma<<<grid, 512, SMEM_TOTAL>>>(b, out, B);
}

// round 14
// speedup vs baseline: 1.0433x; 1.0433x over previous
#include <cuda_runtime.h>
#include <cuda_fp16.h>
#include <cstdint>

#define D_MODEL 1024
#define N_EXP   16
#define MAX_B   32768
#define THRESH  0.3f

// ---- GEMM tiling (fp16 operands, fp32 accum) ----
#define BM 128
#define BN 128
#define BK 64                               // halfs per k-chunk = 128B per row
#define KPAD_H 72                           // 64 + 8 pad halfs (144B rows, conflict-free)
#define A_STG_BYTES (BM * KPAD_H * 2)       // 18432
#define STG_BYTES   (2 * A_STG_BYTES)       // 36864 (A + B)
#define NSTG 2
#define NCH (D_MODEL / BK)                  // 16 k-chunks
#define SMEM_TOTAL (NSTG * STG_BYTES)       // 73728 -> 2 CTAs/SM @ 512 thr
#define NTILES_MAX (MAX_B / BM + N_EXP)     // 272

// ---------------- device-global scratch ----------------
__device__ int    g_counts[N_EXP];
__device__ int    g_tile[MAX_B];
__device__ int    g_rank[MAX_B];
__device__ int    g_perm[MAX_B];
__device__ float  g_qsig[N_EXP * D_MODEL];
__device__ __half g_xh[(size_t)MAX_B * D_MODEL];             // 64 MB fp16 x
__device__ __half g_wh[(size_t)N_EXP * D_MODEL * D_MODEL];   // 32 MB fp16 W

// ---------------- PTX helpers ----------------
__device__ __forceinline__ uint32_t smem_u32(const void* p) {
    uint32_t a;
    asm("{ .reg .u64 t; cvta.to.shared.u64 t, %1; cvt.u32.u64 %0, t; }" : "=r"(a) : "l"(p));
    return a;
}
__device__ __forceinline__ void cpa16(uint32_t dst, const void* src) {
    asm volatile("cp.async.cg.shared.global [%0], [%1], 16;" :: "r"(dst), "l"(src));
}
#define CP_COMMIT() asm volatile("cp.async.commit_group;" ::: "memory")

__device__ __forceinline__ void mma_f16(float* c, const uint32_t* a, const uint32_t* b) {
    asm volatile(
        "mma.sync.aligned.m16n8k16.row.col.f32.f16.f16.f32 "
        "{%0,%1,%2,%3}, {%4,%5,%6,%7}, {%8,%9}, {%0,%1,%2,%3};"
        : "+f"(c[0]), "+f"(c[1]), "+f"(c[2]), "+f"(c[3])
        : "r"(a[0]), "r"(a[1]), "r"(a[2]), "r"(a[3]), "r"(b[0]), "r"(b[1]));
}
__device__ __forceinline__ void ldsm_x4(uint32_t* r, uint32_t addr) {
    asm volatile("ldmatrix.sync.aligned.m8n8.x4.shared.b16 {%0,%1,%2,%3}, [%4];"
                 : "=r"(r[0]), "=r"(r[1]), "=r"(r[2]), "=r"(r[3]) : "r"(addr));
}

// ---------------- convert W fp32->fp16 + zero counts + quantize signatures ----------------
__global__ void convert_w_kernel(const float* __restrict__ W, const float* __restrict__ sig) {
    int gi = blockIdx.x * blockDim.x + threadIdx.x;
    if (gi < N_EXP) g_counts[gi] = 0;
    if (gi < N_EXP * D_MODEL) {
        float s = sig[gi];
        g_qsig[gi] = (s > THRESH) ? 1.0f : ((s < -THRESH) ? -1.0f : 0.0f);
    }
    size_t i = (size_t)gi * 4;
    if (i < (size_t)N_EXP * D_MODEL * D_MODEL) {
        float4 v = *(const float4*)(W + i);
        half2 h0 = __floats2half2_rn(v.x, v.y);
        half2 h1 = __floats2half2_rn(v.z, v.w);
        *(uint2*)(g_wh + i) = make_uint2(*(uint32_t*)&h0, *(uint32_t*)&h1);
    }
}

// ---------------- router: 4 rows per warp, fused x->fp16 ----------------
__global__ void router_kernel(const float* __restrict__ x, int B) {
    const int tid  = threadIdx.x;
    const int warp = tid >> 5;
    const int lane = tid & 31;
    const int row0 = blockIdx.x * 32 + warp * 4;
    if (row0 >= B) return;

    float acc[4][N_EXP];
#pragma unroll
    for (int r = 0; r < 4; r++)
#pragma unroll
        for (int e = 0; e < N_EXP; e++) acc[r][e] = 0.0f;

    const float4* xr[4];
    __half* xh[4];
#pragma unroll
    for (int r = 0; r < 4; r++) {
        int row = row0 + r < B ? row0 + r : B - 1;
        xr[r] = (const float4*)(x + (size_t)row * D_MODEL);
        xh[r] = g_xh + (size_t)row * D_MODEL;
    }

    for (int kk = lane; kk < D_MODEL / 4; kk += 32) {
        float4 xv[4];
#pragma unroll
        for (int r = 0; r < 4; r++) {
            xv[r] = __ldg(&xr[r][kk]);
            half2 h0 = __floats2half2_rn(xv[r].x, xv[r].y);
            half2 h1 = __floats2half2_rn(xv[r].z, xv[r].w);
            *(uint2*)(xh[r] + kk * 4) = make_uint2(*(uint32_t*)&h0, *(uint32_t*)&h1);
        }
#pragma unroll
        for (int e = 0; e < N_EXP; e++) {
            float4 q = *(const float4*)(g_qsig + e * D_MODEL + kk * 4);
#pragma unroll
            for (int r = 0; r < 4; r++)
                acc[r][e] += xv[r].x * q.x + xv[r].y * q.y + xv[r].z * q.z + xv[r].w * q.w;
        }
    }

#pragma unroll
    for (int r = 0; r < 4; r++) {
#pragma unroll
        for (int e = 0; e < N_EXP; e++) {
#pragma unroll
            for (int off = 16; off >= 1; off >>= 1)
                acc[r][e] += __shfl_xor_sync(0xffffffffu, acc[r][e], off);
        }
        if (lane == 0 && row0 + r < B) {
            int best = 0;
            float bv = acc[r][0];
#pragma unroll
            for (int e = 1; e < N_EXP; e++)
                if (acc[r][e] > bv) { bv = acc[r][e]; best = e; }  // first max wins
            g_tile[row0 + r] = best;
            g_rank[row0 + r] = atomicAdd(&g_counts[best], 1);
        }
    }
}

// ---------------- scatter: offsets recomputed inline from g_counts ----------------
__global__ void scatter_kernel(int B, float* __restrict__ tail) {
    int row = blockIdx.x * blockDim.x + threadIdx.x;
    if (row >= B) return;
    int offs = 0, e = g_tile[row];
#pragma unroll
    for (int i = 0; i < N_EXP; i++)
        if (i < e) offs += g_counts[i];
    g_perm[offs + g_rank[row]] = row;
    if (tail) tail[row] = (float)e;
}

// ---------------- fp16 mma.sync expert GEMM: 512 thr, 16 warps 4x4, 2-stage ----
__global__ void __launch_bounds__(512, 2) expert_gemm_mma(
    const float* __restrict__ bias, float* __restrict__ out, int B)
{
    // ---- inline flat-tile scheduler from g_counts ----
    const int bx = blockIdx.x;
    int e = 0, m0 = 0, base = 0, cnt = 0;
    {
        int ts = 0, s = 0;
        bool found = false;
#pragma unroll
        for (int i = 0; i < N_EXP; i++) {
            int c  = g_counts[i];
            int nt = (c + BM - 1) / BM;
            if (!found && bx < ts + nt) { e = i; m0 = (bx - ts) * BM; base = s; cnt = c; found = true; }
            ts += nt; s += c;
        }
        if (!found) return;
    }
    const int n0  = blockIdx.y * BN;
    const int rem = cnt - m0;

    extern __shared__ char smem[];
    const uint32_t sb = smem_u32(smem);

    const int tid  = threadIdx.x;
    const int wid  = tid >> 5;
    const int lane = tid & 31;
    const int warp_m = wid >> 2;           // 0..3 (32-row quarters)
    const int warp_n = wid & 3;            // 0..3 (32-col quarters)

    // ---- loader: threads 0-255 load A (gathered rows), 256-511 load B ----
    const int lt    = tid & 255;
    const int lrow  = lt >> 1;             // 0..127
    const int lsegB = (lt & 1) * 64;       // 0 or 64 within the 128B k-chunk row
    const bool isA  = tid < 256;
    const char* src;
    if (isA) {
        const int arloc = (lrow < rem) ? lrow : (rem - 1);
        src = (const char*)(g_xh + (size_t)__ldg(&g_perm[base + m0 + arloc]) * D_MODEL) + lsegB;
    } else {
        src = (const char*)(g_wh + ((size_t)e * D_MODEL + (size_t)(n0 + lrow)) * D_MODEL) + lsegB;
    }
    const uint32_t dst = sb + (isA ? 0u : (uint32_t)A_STG_BYTES)
                       + (uint32_t)lrow * (KPAD_H * 2) + lsegB;

    // ---- ldmatrix per-lane offsets (halfs, within stage) ----
    const int q8 = lane >> 3;
    const int r8 = lane & 7;
    const uint32_t aoffH = (uint32_t)((warp_m * 32 + (q8 & 1) * 8 + r8) * KPAD_H + (q8 >> 1) * 8);
    const uint32_t boffH = (uint32_t)((warp_n * 32 + (q8 >> 1) * 8 + r8) * KPAD_H + (q8 & 1) * 8);

    // prologue: chunk 0 -> stage 0
#pragma unroll
    for (int s = 0; s < 4; s++) cpa16(dst + s * 16, src + s * 16);
    CP_COMMIT();

    float acc[2][4][4];
#pragma unroll
    for (int i = 0; i < 2; i++)
#pragma unroll
        for (int j = 0; j < 4; j++)
#pragma unroll
            for (int r = 0; r < 4; r++) acc[i][j][r] = 0.0f;

    for (int c = 0; c < NCH; c++) {
        asm volatile("cp.async.wait_group 0;" ::: "memory");
        __syncthreads();

        if (c + 1 < NCH) {                 // prefetch c+1 into the other stage
            const uint32_t so = (uint32_t)((c + 1) & 1) * STG_BYTES;
            const char* p = src + (size_t)(c + 1) * 128;
#pragma unroll
            for (int s = 0; s < 4; s++) cpa16(dst + so + s * 16, p + s * 16);
            CP_COMMIT();
        }

        const uint32_t sA = sb + (uint32_t)(c & 1) * STG_BYTES;
        const uint32_t sB = sA + A_STG_BYTES;

#pragma unroll
        for (int s = 0; s < 4; s++) {
            const int k0 = s * 16;
            uint32_t af[2][4], bf[4][2];
#pragma unroll
            for (int mf = 0; mf < 2; mf++)
                ldsm_x4(af[mf], sA + (aoffH + (uint32_t)(mf * 16) * KPAD_H + k0) * 2);
#pragma unroll
            for (int p = 0; p < 2; p++) {
                uint32_t bq[4];
                ldsm_x4(bq, sB + (boffH + (uint32_t)(p * 16) * KPAD_H + k0) * 2);
                bf[p * 2 + 0][0] = bq[0]; bf[p * 2 + 0][1] = bq[1];
                bf[p * 2 + 1][0] = bq[2]; bf[p * 2 + 1][1] = bq[3];
            }
#pragma unroll
            for (int mf = 0; mf < 2; mf++)
#pragma unroll
                for (int nf = 0; nf < 4; nf++)
                    mma_f16(acc[mf][nf], af[mf], bf[nf]);
        }
    }

    // ---- fused epilogue: +bias, relu, +residual (fp16 cache), scatter ----
    const int t = lane & 3;
    const int g = lane >> 2;
    const float* bias_e = bias + e * D_MODEL;
    float2 bb[4];
#pragma unroll
    for (int nf = 0; nf < 4; nf++)
        bb[nf] = *(const float2*)(bias_e + n0 + warp_n * 32 + nf * 8 + t * 2);

#pragma unroll
    for (int mf = 0; mf < 2; mf++) {
#pragma unroll
        for (int h = 0; h < 2; h++) {
            const int rloc = warp_m * 32 + mf * 16 + g + h * 8;
            if (rloc >= rem) continue;
            const int gr = __ldg(&g_perm[base + m0 + rloc]);
            const __half* xhr = g_xh + (size_t)gr * D_MODEL;
            float*        orow = out + (size_t)gr * D_MODEL;
#pragma unroll
            for (int nf = 0; nf < 4; nf++) {
                const int col = n0 + warp_n * 32 + nf * 8 + t * 2;
                const float2 xx = __half22float2(*(const half2*)(xhr + col));
                float v0 = fmaxf(acc[mf][nf][h * 2 + 0] + bb[nf].x, 0.0f) + xx.x;
                float v1 = fmaxf(acc[mf][nf][h * 2 + 1] + bb[nf].y, 0.0f) + xx.y;
                *(float2*)(orow + col) = make_float2(v0, v1);
            }
        }
    }
}

// ---------------- launch ----------------
extern "C" void kernel_launch(void* const* d_in, const int* in_sizes, int n_in,
                              void* d_out, int out_size) {
    const float* x   = (const float*)d_in[0];
    const float* sig = (const float*)d_in[1];
    const float* W   = (const float*)d_in[2];
    const float* b   = (const float*)d_in[3];
    float* out = (float*)d_out;

    const int B = in_sizes[0] / D_MODEL;

    cudaFuncSetAttribute(expert_gemm_mma,
                         cudaFuncAttributeMaxDynamicSharedMemorySize, SMEM_TOTAL);

    convert_w_kernel<<<(N_EXP * D_MODEL * D_MODEL / 4 + 255) / 256, 256>>>(W, sig);
    router_kernel<<<(B + 31) / 32, 256>>>(x, B);

    float* tail = nullptr;
    if ((long long)out_size >= (long long)B * D_MODEL + B)
        tail = out + (size_t)B * D_MODEL;
    scatter_kernel<<<(B + 255) / 256, 256>>>(B, tail);

    dim3 grid(NTILES_MAX, D_MODEL / BN);
    expert_gemm_mma<<<grid, 512, SMEM_TOTAL>>>(b, out, B);
}

// round 15
// speedup vs baseline: 1.0643x; 1.0201x over previous
#include <cuda_runtime.h>
#include <cuda_fp16.h>
#include <cstdint>

#define D_MODEL 1024
#define N_EXP   16
#define MAX_B   32768
#define THRESH  0.3f

// ---- GEMM tiling (fp16 operands, fp32 accum) ----
#define BM 128
#define BN 128
#define BK 64                               // halfs per k-chunk = 128B per row
#define KPAD_H 72                           // 64 + 8 pad halfs (144B rows, conflict-free)
#define A_STG_BYTES (BM * KPAD_H * 2)       // 18432
#define STG_BYTES   (2 * A_STG_BYTES)       // 36864 (A + B)
#define NSTG 2
#define NCH (D_MODEL / BK)                  // 16 k-chunks
#define SMEM_TOTAL (NSTG * STG_BYTES)       // 73728 -> 2 CTAs/SM @ 512 thr
#define NTILES_MAX (MAX_B / BM + N_EXP)     // 272

// ---------------- device-global scratch ----------------
__device__ int    g_counts[N_EXP];
__device__ int    g_tile[MAX_B];
__device__ int    g_rank[MAX_B];
__device__ int    g_perm[MAX_B];
__device__ float  g_qsig[N_EXP * D_MODEL];
__device__ __half g_xh[(size_t)MAX_B * D_MODEL];             // 64 MB fp16 x
__device__ __half g_wh[(size_t)N_EXP * D_MODEL * D_MODEL];   // 32 MB fp16 W

// ---------------- side stream for convert/router overlap (created pre-main) ----
static cudaStream_t g_s2  = nullptr;
static cudaEvent_t  g_evF = nullptr;
static cudaEvent_t  g_evJ = nullptr;
namespace {
struct SideInit {
    SideInit() {
        if (cudaStreamCreateWithFlags(&g_s2, cudaStreamNonBlocking) != cudaSuccess) {
            g_s2 = nullptr; return;
        }
        if (cudaEventCreateWithFlags(&g_evF, cudaEventDisableTiming) != cudaSuccess ||
            cudaEventCreateWithFlags(&g_evJ, cudaEventDisableTiming) != cudaSuccess) {
            g_s2 = nullptr;
        }
    }
};
static SideInit g_side_init;
}

// ---------------- PTX helpers ----------------
__device__ __forceinline__ uint32_t smem_u32(const void* p) {
    uint32_t a;
    asm("{ .reg .u64 t; cvta.to.shared.u64 t, %1; cvt.u32.u64 %0, t; }" : "=r"(a) : "l"(p));
    return a;
}
__device__ __forceinline__ void cpa16(uint32_t dst, const void* src) {
    asm volatile("cp.async.cg.shared.global [%0], [%1], 16;" :: "r"(dst), "l"(src));
}
#define CP_COMMIT() asm volatile("cp.async.commit_group;" ::: "memory")

__device__ __forceinline__ void mma_f16(float* c, const uint32_t* a, const uint32_t* b) {
    asm volatile(
        "mma.sync.aligned.m16n8k16.row.col.f32.f16.f16.f32 "
        "{%0,%1,%2,%3}, {%4,%5,%6,%7}, {%8,%9}, {%0,%1,%2,%3};"
        : "+f"(c[0]), "+f"(c[1]), "+f"(c[2]), "+f"(c[3])
        : "r"(a[0]), "r"(a[1]), "r"(a[2]), "r"(a[3]), "r"(b[0]), "r"(b[1]));
}
__device__ __forceinline__ void ldsm_x4(uint32_t* r, uint32_t addr) {
    asm volatile("ldmatrix.sync.aligned.m8n8.x4.shared.b16 {%0,%1,%2,%3}, [%4];"
                 : "=r"(r[0]), "=r"(r[1]), "=r"(r[2]), "=r"(r[3]) : "r"(addr));
}

// ---------------- setup: zero counts + quantize signatures ----------------
__global__ void setup_kernel(const float* __restrict__ sig) {
    int i = blockIdx.x * blockDim.x + threadIdx.x;
    if (i < N_EXP) g_counts[i] = 0;
    if (i < N_EXP * D_MODEL) {
        float s = sig[i];
        g_qsig[i] = (s > THRESH) ? 1.0f : ((s < -THRESH) ? -1.0f : 0.0f);
    }
}

// ---------------- W fp32 -> fp16 (runs on side stream, overlapped w/ router) ----
__global__ void convert_w_kernel(const float* __restrict__ W) {
    size_t i = (size_t)(blockIdx.x * blockDim.x + threadIdx.x) * 4;
    if (i < (size_t)N_EXP * D_MODEL * D_MODEL) {
        float4 v = *(const float4*)(W + i);
        half2 h0 = __floats2half2_rn(v.x, v.y);
        half2 h1 = __floats2half2_rn(v.z, v.w);
        *(uint2*)(g_wh + i) = make_uint2(*(uint32_t*)&h0, *(uint32_t*)&h1);
    }
}

// ---------------- router: 4 rows per warp, fused x->fp16 ----------------
__global__ void router_kernel(const float* __restrict__ x, int B) {
    const int tid  = threadIdx.x;
    const int warp = tid >> 5;
    const int lane = tid & 31;
    const int row0 = blockIdx.x * 32 + warp * 4;
    if (row0 >= B) return;

    float acc[4][N_EXP];
#pragma unroll
    for (int r = 0; r < 4; r++)
#pragma unroll
        for (int e = 0; e < N_EXP; e++) acc[r][e] = 0.0f;

    const float4* xr[4];
    __half* xh[4];
#pragma unroll
    for (int r = 0; r < 4; r++) {
        int row = row0 + r < B ? row0 + r : B - 1;
        xr[r] = (const float4*)(x + (size_t)row * D_MODEL);
        xh[r] = g_xh + (size_t)row * D_MODEL;
    }

    for (int kk = lane; kk < D_MODEL / 4; kk += 32) {
        float4 xv[4];
#pragma unroll
        for (int r = 0; r < 4; r++) {
            xv[r] = __ldg(&xr[r][kk]);
            half2 h0 = __floats2half2_rn(xv[r].x, xv[r].y);
            half2 h1 = __floats2half2_rn(xv[r].z, xv[r].w);
            *(uint2*)(xh[r] + kk * 4) = make_uint2(*(uint32_t*)&h0, *(uint32_t*)&h1);
        }
#pragma unroll
        for (int e = 0; e < N_EXP; e++) {
            float4 q = *(const float4*)(g_qsig + e * D_MODEL + kk * 4);
#pragma unroll
            for (int r = 0; r < 4; r++)
                acc[r][e] += xv[r].x * q.x + xv[r].y * q.y + xv[r].z * q.z + xv[r].w * q.w;
        }
    }

#pragma unroll
    for (int r = 0; r < 4; r++) {
#pragma unroll
        for (int e = 0; e < N_EXP; e++) {
#pragma unroll
            for (int off = 16; off >= 1; off >>= 1)
                acc[r][e] += __shfl_xor_sync(0xffffffffu, acc[r][e], off);
        }
        if (lane == 0 && row0 + r < B) {
            int best = 0;
            float bv = acc[r][0];
#pragma unroll
            for (int e = 1; e < N_EXP; e++)
                if (acc[r][e] > bv) { bv = acc[r][e]; best = e; }  // first max wins
            g_tile[row0 + r] = best;
            g_rank[row0 + r] = atomicAdd(&g_counts[best], 1);
        }
    }
}

// ---------------- scatter: offsets recomputed inline from g_counts ----------------
__global__ void scatter_kernel(int B, float* __restrict__ tail) {
    int row = blockIdx.x * blockDim.x + threadIdx.x;
    if (row >= B) return;
    int offs = 0, e = g_tile[row];
#pragma unroll
    for (int i = 0; i < N_EXP; i++)
        if (i < e) offs += g_counts[i];
    g_perm[offs + g_rank[row]] = row;
    if (tail) tail[row] = (float)e;
}

// ---------------- fp16 mma.sync expert GEMM: 512 thr, 16 warps 4x4, 2-stage ----
__global__ void __launch_bounds__(512, 2) expert_gemm_mma(
    const float* __restrict__ bias, float* __restrict__ out, int B)
{
    // ---- inline flat-tile scheduler from g_counts ----
    const int bx = blockIdx.x;
    int e = 0, m0 = 0, base = 0, cnt = 0;
    {
        int ts = 0, s = 0;
        bool found = false;
#pragma unroll
        for (int i = 0; i < N_EXP; i++) {
            int c  = g_counts[i];
            int nt = (c + BM - 1) / BM;
            if (!found && bx < ts + nt) { e = i; m0 = (bx - ts) * BM; base = s; cnt = c; found = true; }
            ts += nt; s += c;
        }
        if (!found) return;
    }
    const int n0  = blockIdx.y * BN;
    const int rem = cnt - m0;

    extern __shared__ char smem[];
    const uint32_t sb = smem_u32(smem);

    const int tid  = threadIdx.x;
    const int wid  = tid >> 5;
    const int lane = tid & 31;
    const int warp_m = wid >> 2;           // 0..3 (32-row quarters)
    const int warp_n = wid & 3;            // 0..3 (32-col quarters)

    // ---- loader: threads 0-255 load A (gathered rows), 256-511 load B ----
    const int lt    = tid & 255;
    const int lrow  = lt >> 1;             // 0..127
    const int lsegB = (lt & 1) * 64;       // 0 or 64 within the 128B k-chunk row
    const bool isA  = tid < 256;
    const char* src;
    if (isA) {
        const int arloc = (lrow < rem) ? lrow : (rem - 1);
        src = (const char*)(g_xh + (size_t)__ldg(&g_perm[base + m0 + arloc]) * D_MODEL) + lsegB;
    } else {
        src = (const char*)(g_wh + ((size_t)e * D_MODEL + (size_t)(n0 + lrow)) * D_MODEL) + lsegB;
    }
    const uint32_t dst = sb + (isA ? 0u : (uint32_t)A_STG_BYTES)
                       + (uint32_t)lrow * (KPAD_H * 2) + lsegB;

    // ---- ldmatrix per-lane offsets (halfs, within stage) ----
    const int q8 = lane >> 3;
    const int r8 = lane & 7;
    const uint32_t aoffH = (uint32_t)((warp_m * 32 + (q8 & 1) * 8 + r8) * KPAD_H + (q8 >> 1) * 8);
    const uint32_t boffH = (uint32_t)((warp_n * 32 + (q8 >> 1) * 8 + r8) * KPAD_H + (q8 & 1) * 8);

    // prologue: chunk 0 -> stage 0
#pragma unroll
    for (int s = 0; s < 4; s++) cpa16(dst + s * 16, src + s * 16);
    CP_COMMIT();

    float acc[2][4][4];
#pragma unroll
    for (int i = 0; i < 2; i++)
#pragma unroll
        for (int j = 0; j < 4; j++)
#pragma unroll
            for (int r = 0; r < 4; r++) acc[i][j][r] = 0.0f;

    for (int c = 0; c < NCH; c++) {
        asm volatile("cp.async.wait_group 0;" ::: "memory");
        __syncthreads();

        if (c + 1 < NCH) {                 // prefetch c+1 into the other stage
            const uint32_t so = (uint32_t)((c + 1) & 1) * STG_BYTES;
            const char* p = src + (size_t)(c + 1) * 128;
#pragma unroll
            for (int s = 0; s < 4; s++) cpa16(dst + so + s * 16, p + s * 16);
            CP_COMMIT();
        }

        const uint32_t sA = sb + (uint32_t)(c & 1) * STG_BYTES;
        const uint32_t sB = sA + A_STG_BYTES;

#pragma unroll
        for (int s = 0; s < 4; s++) {
            const int k0 = s * 16;
            uint32_t af[2][4], bf[4][2];
#pragma unroll
            for (int mf = 0; mf < 2; mf++)
                ldsm_x4(af[mf], sA + (aoffH + (uint32_t)(mf * 16) * KPAD_H + k0) * 2);
#pragma unroll
            for (int p = 0; p < 2; p++) {
                uint32_t bq[4];
                ldsm_x4(bq, sB + (boffH + (uint32_t)(p * 16) * KPAD_H + k0) * 2);
                bf[p * 2 + 0][0] = bq[0]; bf[p * 2 + 0][1] = bq[1];
                bf[p * 2 + 1][0] = bq[2]; bf[p * 2 + 1][1] = bq[3];
            }
#pragma unroll
            for (int mf = 0; mf < 2; mf++)
#pragma unroll
                for (int nf = 0; nf < 4; nf++)
                    mma_f16(acc[mf][nf], af[mf], bf[nf]);
        }
    }

    // ---- fused epilogue: +bias, relu, +residual (fp16 cache), scatter ----
    const int t = lane & 3;
    const int g = lane >> 2;
    const float* bias_e = bias + e * D_MODEL;
    float2 bb[4];
#pragma unroll
    for (int nf = 0; nf < 4; nf++)
        bb[nf] = *(const float2*)(bias_e + n0 + warp_n * 32 + nf * 8 + t * 2);

#pragma unroll
    for (int mf = 0; mf < 2; mf++) {
#pragma unroll
        for (int h = 0; h < 2; h++) {
            const int rloc = warp_m * 32 + mf * 16 + g + h * 8;
            if (rloc >= rem) continue;
            const int gr = __ldg(&g_perm[base + m0 + rloc]);
            const __half* xhr = g_xh + (size_t)gr * D_MODEL;
            float*        orow = out + (size_t)gr * D_MODEL;
#pragma unroll
            for (int nf = 0; nf < 4; nf++) {
                const int col = n0 + warp_n * 32 + nf * 8 + t * 2;
                const float2 xx = __half22float2(*(const half2*)(xhr + col));
                float v0 = fmaxf(acc[mf][nf][h * 2 + 0] + bb[nf].x, 0.0f) + xx.x;
                float v1 = fmaxf(acc[mf][nf][h * 2 + 1] + bb[nf].y, 0.0f) + xx.y;
                *(float2*)(orow + col) = make_float2(v0, v1);
            }
        }
    }
}

// ---------------- launch ----------------
extern "C" void kernel_launch(void* const* d_in, const int* in_sizes, int n_in,
                              void* d_out, int out_size) {
    const float* x   = (const float*)d_in[0];
    const float* sig = (const float*)d_in[1];
    const float* W   = (const float*)d_in[2];
    const float* b   = (const float*)d_in[3];
    float* out = (float*)d_out;

    const int B = in_sizes[0] / D_MODEL;

    cudaFuncSetAttribute(expert_gemm_mma,
                         cudaFuncAttributeMaxDynamicSharedMemorySize, SMEM_TOTAL);

    const int convGrid = (N_EXP * D_MODEL * D_MODEL / 4 + 255) / 256;

    if (g_s2) {
        // fork: convert_w on side stream, overlapped with setup+router on main
        cudaEventRecord(g_evF, 0);
        cudaStreamWaitEvent(g_s2, g_evF, 0);
        convert_w_kernel<<<convGrid, 256, 0, g_s2>>>(W);
        cudaEventRecord(g_evJ, g_s2);
    } else {
        convert_w_kernel<<<convGrid, 256>>>(W);
    }

    setup_kernel<<<(N_EXP * D_MODEL + 255) / 256, 256>>>(sig);
    router_kernel<<<(B + 31) / 32, 256>>>(x, B);

    float* tail = nullptr;
    if ((long long)out_size >= (long long)B * D_MODEL + B)
        tail = out + (size_t)B * D_MODEL;
    scatter_kernel<<<(B + 255) / 256, 256>>>(B, tail);

    if (g_s2) cudaStreamWaitEvent(0, g_evJ, 0);   // join before GEMM consumes g_wh

    dim3 grid(NTILES_MAX, D_MODEL / BN);
    expert_gemm_mma<<<grid, 512, SMEM_TOTAL>>>(b, out, B);
}